// round 16
// baseline (speedup 1.0000x reference)
#include <cuda_runtime.h>
#include <cuda_bf16.h>
#include <math.h>
#include <stdint.h>

// Problem constants
#define BV   2
#define NV   2048
#define CV   1024
#define HV   16
#define HDV  64
#define MROWS (BV*NV)            // 4096
#define SM_SCALE 0.1803368801f   // 64^-0.5 * log2(e)
#define BHND ((size_t)BV*HV*NV*HDV)

// scratch
__device__ float g_o[(size_t)MROWS*CV];           // attention output fp32
__device__ float g_w2[(size_t)CV*3*CV];           // LoRA-folded QKV weight
__device__ float g_b2[3*CV];                      // LoRA-folded QKV bias
// split-bf16 q/k/v (hi + lo residual), layout [B,H,N,HD]
__device__ __nv_bfloat16 g_qh[BHND], g_ql[BHND];
__device__ __nv_bfloat16 g_kh[BHND], g_kl[BHND];
__device__ __nv_bfloat16 g_vh[BHND], g_vl[BHND];

// ---------------------------------------------------------------------------
// helpers
// ---------------------------------------------------------------------------
__device__ __forceinline__ void ldsm4(uint32_t r[4], const void* p) {
    uint32_t a = (uint32_t)__cvta_generic_to_shared(p);
    asm volatile("ldmatrix.sync.aligned.m8n8.x4.shared.b16 {%0,%1,%2,%3},[%4];"
        : "=r"(r[0]), "=r"(r[1]), "=r"(r[2]), "=r"(r[3]) : "r"(a));
}
__device__ __forceinline__ void ldsm4t(uint32_t r[4], const void* p) {
    uint32_t a = (uint32_t)__cvta_generic_to_shared(p);
    asm volatile("ldmatrix.sync.aligned.m8n8.x4.trans.shared.b16 {%0,%1,%2,%3},[%4];"
        : "=r"(r[0]), "=r"(r[1]), "=r"(r[2]), "=r"(r[3]) : "r"(a));
}
__device__ __forceinline__ void mma_bf16(float d[4],
    uint32_t a0, uint32_t a1, uint32_t a2, uint32_t a3, uint32_t b0, uint32_t b1)
{
    asm volatile(
        "mma.sync.aligned.m16n8k16.row.col.f32.bf16.bf16.f32 "
        "{%0,%1,%2,%3},{%4,%5,%6,%7},{%8,%9},{%0,%1,%2,%3};"
        : "+f"(d[0]), "+f"(d[1]), "+f"(d[2]), "+f"(d[3])
        : "r"(a0), "r"(a1), "r"(a2), "r"(a3), "r"(b0), "r"(b1));
}
__device__ __forceinline__ float ex2f(float x) {
    float r; asm("ex2.approx.ftz.f32 %0,%1;" : "=f"(r) : "f"(x)); return r;
}
__device__ __forceinline__ void packsplit(float x, float y, uint32_t& hp, uint32_t& lp)
{
    __nv_bfloat162 h = __floats2bfloat162_rn(x, y);
    __nv_bfloat162 l = __floats2bfloat162_rn(x - __bfloat162float(h.x),
                                             y - __bfloat162float(h.y));
    hp = *reinterpret_cast<uint32_t*>(&h);
    lp = *reinterpret_cast<uint32_t*>(&l);
}
__device__ __forceinline__ void split_store4(__nv_bfloat16* H, __nv_bfloat16* L,
                                             int off, float4 v)
{
    __nv_bfloat162 h0 = __floats2bfloat162_rn(v.x, v.y);
    __nv_bfloat162 h1 = __floats2bfloat162_rn(v.z, v.w);
    __nv_bfloat162 l0 = __floats2bfloat162_rn(v.x - __bfloat162float(h0.x),
                                              v.y - __bfloat162float(h0.y));
    __nv_bfloat162 l1 = __floats2bfloat162_rn(v.z - __bfloat162float(h1.x),
                                              v.w - __bfloat162float(h1.y));
    *reinterpret_cast<__nv_bfloat162*>(H + off)     = h0;
    *reinterpret_cast<__nv_bfloat162*>(H + off + 2) = h1;
    *reinterpret_cast<__nv_bfloat162*>(L + off)     = l0;
    *reinterpret_cast<__nv_bfloat162*>(L + off + 2) = l1;
}
__device__ __forceinline__ void cpa16(uint32_t dsh, const void* src) {
    asm volatile("cp.async.cg.shared.global [%0], [%1], 16;" :: "r"(dsh), "l"(src));
}

// ---------------------------------------------------------------------------
// prep: fold LoRA into QKV weights.
// ---------------------------------------------------------------------------
__global__ __launch_bounds__(256) void prep_w_kernel(
    const float* __restrict__ W,
    const float* __restrict__ aq, const float* __restrict__ bq,
    const float* __restrict__ av, const float* __restrict__ bv)
{
    __shared__ float Ws[64][65];
    __shared__ float Ms[64][65];

    const int tid = threadIdx.x;
    const int c0  = blockIdx.x * 64;
    const int r0  = blockIdx.y * 64;
    const int which = c0 >> 10;          // 0=q,1=k,2=v

    if (which == 1) {
        for (int ii = 0; ii < 4; ++ii) {
            const int idx = tid + ii * 256;
            const int i = idx >> 4, e4 = (idx & 15) * 4;
            float4 v = *reinterpret_cast<const float4*>(
                W + (size_t)(r0 + i) * 3072 + c0 + e4);
            *reinterpret_cast<float4*>(
                g_w2 + (size_t)(r0 + i) * 3072 + c0 + e4) = v;
        }
        return;
    }
    const float* A  = (which == 0) ? aq : av;
    const float* Bm = (which == 0) ? bq : bv;

    for (int ii = 0; ii < 4; ++ii) {
        const int idx = tid + ii * 256;
        const int i = idx >> 4, e4 = (idx & 15) * 4;
        float4 v = *reinterpret_cast<const float4*>(
            W + (size_t)(r0 + i) * 3072 + c0 + e4);
        Ws[i][e4+0]=v.x; Ws[i][e4+1]=v.y; Ws[i][e4+2]=v.z; Ws[i][e4+3]=v.w;
    }
    for (int ii = 0; ii < 16; ++ii) {
        const int idx = tid + ii * 256;
        const int e = idx >> 6, d = idx & 63;
        float s = 0.f;
        for (int r = 0; r < 16; ++r) s += A[e * 16 + r] * Bm[r * 64 + d];
        Ms[e][d] = (e == d ? 1.f : 0.f) + 2.f * s;
    }
    __syncthreads();

    const int i  = tid & 63;
    const int dg = tid >> 6;
    for (int jj = 0; jj < 16; ++jj) {
        const int col = dg * 16 + jj;
        float acc = 0.f;
        for (int e = 0; e < 64; ++e) acc += Ws[i][e] * Ms[e][col];
        g_w2[(size_t)(r0 + i) * 3072 + c0 + col] = acc;
    }
}

__global__ __launch_bounds__(64) void prep_b_kernel(
    const float* __restrict__ bqkv,
    const float* __restrict__ aq, const float* __restrict__ bq,
    const float* __restrict__ av, const float* __restrict__ bv)
{
    __shared__ float rs[16];
    const int base = blockIdx.x * 64;
    const int d    = threadIdx.x;
    const int which = (base + d) >> 10;
    if (which == 1) { g_b2[base + d] = bqkv[base + d]; return; }
    const float* A  = (which == 0) ? aq : av;
    const float* Bm = (which == 0) ? bq : bv;
    if (d < 16) {
        float s = 0.f;
        for (int e = 0; e < 64; ++e) s += bqkv[base + e] * A[e * 16 + d];
        rs[d] = s;
    }
    __syncthreads();
    float delta = 0.f;
    for (int j = 0; j < 16; ++j) delta += rs[j] * Bm[j * 64 + d];
    g_b2[base + d] = bqkv[base + d] + 2.f * delta;
}

// ---------------------------------------------------------------------------
// split-bf16 GEMM, DOUBLE-BUFFERED (1 sync per k-tile).  Block 128x128,
// K-step 32, 8 warps, 2 smem stages (dynamic 75776 B), 2 CTAs/SM.
// Loop: LDG A(k+1) | MMA ks=0 | cvt/STS A | LDG B(k+1) | MMA ks=1 |
//       cvt/STS B | sync.
// ---------------------------------------------------------------------------
#define GSTG  18944                     // halves per stage
#define GSMEM (2 * GSTG * 2)            // 75776 bytes

__global__ __launch_bounds__(256, 2) void gemm3_kernel(
    const float* __restrict__ Ain, const float* __restrict__ Bin,
    const float* __restrict__ biasin, float* __restrict__ Cout,
    int Ncols, int mode)
{
    extern __shared__ __nv_bfloat16 sm[];
    // stage layout (halves): sAh 0..5120, sAl 5120..10240,
    //                        sBh 10240..14592, sBl 14592..18944

    const float* A    = Ain ? Ain : g_o;
    const float* B    = Bin ? Bin : g_w2;
    const float* bias = Bin ? biasin : g_b2;

    const int tid  = threadIdx.x;
    const int lane = tid & 31;
    const int warp = tid >> 5;
    const int m0   = (warp >> 2) * 64;
    const int n0   = (warp & 3) * 32;
    const int rB   = blockIdx.y * 128;
    const int cB   = blockIdx.x * 128;

    float acc[4][4][4];
    #pragma unroll
    for (int i = 0; i < 4; ++i)
        #pragma unroll
        for (int j = 0; j < 4; ++j)
            #pragma unroll
            for (int r = 0; r < 4; ++r) acc[i][j][r] = 0.f;

    const int arow = tid >> 3, acol = (tid & 7) * 4;
    const int brow = tid >> 5, bcol = (tid & 31) * 4;

    // prologue: fill stage 0 with tile k=0
    {
        __nv_bfloat16* sAh = sm;
        __nv_bfloat16* sAl = sm + 5120;
        __nv_bfloat16* sBh = sm + 10240;
        __nv_bfloat16* sBl = sm + 14592;
        #pragma unroll
        for (int i = 0; i < 4; ++i) {
            const int r = arow + i * 32;
            float4 v = *reinterpret_cast<const float4*>(
                A + (size_t)(rB + r) * 1024 + acol);
            split_store4(sAh, sAl, r * 40 + acol, v);
        }
        #pragma unroll
        for (int i = 0; i < 4; ++i) {
            const int r = brow + i * 8;
            float4 v = *reinterpret_cast<const float4*>(
                B + (size_t)r * Ncols + cB + bcol);
            split_store4(sBh, sBl, r * 136 + bcol, v);
        }
    }
    __syncthreads();

    for (int k = 0; k < 32; ++k) {
        const __nv_bfloat16* cAh = sm + (k & 1) * GSTG;
        const __nv_bfloat16* cAl = cAh + 5120;
        const __nv_bfloat16* cBh = cAh + 10240;
        const __nv_bfloat16* cBl = cAh + 14592;
        __nv_bfloat16* nAh = sm + ((k + 1) & 1) * GSTG;
        __nv_bfloat16* nAl = nAh + 5120;
        __nv_bfloat16* nBh = nAh + 10240;
        __nv_bfloat16* nBl = nAh + 14592;
        const int kn = (k + 1) * 32;
        const bool more = (k < 31);

        // --- prefetch A(k+1) ---
        float4 va[4];
        if (more) {
            #pragma unroll
            for (int i = 0; i < 4; ++i)
                va[i] = *reinterpret_cast<const float4*>(
                    A + (size_t)(rB + arow + i * 32) * 1024 + kn + acol);
        }

        // --- MMA ks = 0 on current stage ---
        #pragma unroll
        for (int ks = 0; ks < 1; ++ks) { }
        {
            uint32_t ah[4][4], al[4][4];
            #pragma unroll
            for (int mi = 0; mi < 4; ++mi) {
                const int off = (m0 + mi * 16 + (lane & 15)) * 40
                              + ((lane >> 4) << 3);
                ldsm4(ah[mi], cAh + off);
                ldsm4(al[mi], cAl + off);
            }
            uint32_t bh[4][2], bl[4][2];
            #pragma unroll
            for (int Jp = 0; Jp < 2; ++Jp) {
                const int off = ((lane & 15)) * 136
                              + n0 + Jp * 16 + ((lane >> 4) << 3);
                uint32_t t[4];
                ldsm4t(t, cBh + off);
                bh[2*Jp][0] = t[0]; bh[2*Jp][1] = t[1];
                bh[2*Jp+1][0] = t[2]; bh[2*Jp+1][1] = t[3];
                ldsm4t(t, cBl + off);
                bl[2*Jp][0] = t[0]; bl[2*Jp][1] = t[1];
                bl[2*Jp+1][0] = t[2]; bl[2*Jp+1][1] = t[3];
            }
            #pragma unroll
            for (int mi = 0; mi < 4; ++mi)
                #pragma unroll
                for (int nj = 0; nj < 4; ++nj) {
                    mma_bf16(acc[mi][nj], ah[mi][0], ah[mi][1], ah[mi][2], ah[mi][3],
                             bh[nj][0], bh[nj][1]);
                    mma_bf16(acc[mi][nj], ah[mi][0], ah[mi][1], ah[mi][2], ah[mi][3],
                             bl[nj][0], bl[nj][1]);
                    mma_bf16(acc[mi][nj], al[mi][0], al[mi][1], al[mi][2], al[mi][3],
                             bh[nj][0], bh[nj][1]);
                }
        }

        // --- store converted A(k+1) ---
        if (more) {
            #pragma unroll
            for (int i = 0; i < 4; ++i)
                split_store4(nAh, nAl, (arow + i * 32) * 40 + acol, va[i]);
        }

        // --- prefetch B(k+1) ---
        float4 vb[4];
        if (more) {
            #pragma unroll
            for (int i = 0; i < 4; ++i)
                vb[i] = *reinterpret_cast<const float4*>(
                    B + (size_t)(kn + brow + i * 8) * Ncols + cB + bcol);
        }

        // --- MMA ks = 1 on current stage ---
        {
            uint32_t ah[4][4], al[4][4];
            #pragma unroll
            for (int mi = 0; mi < 4; ++mi) {
                const int off = (m0 + mi * 16 + (lane & 15)) * 40
                              + 16 + ((lane >> 4) << 3);
                ldsm4(ah[mi], cAh + off);
                ldsm4(al[mi], cAl + off);
            }
            uint32_t bh[4][2], bl[4][2];
            #pragma unroll
            for (int Jp = 0; Jp < 2; ++Jp) {
                const int off = (16 + (lane & 15)) * 136
                              + n0 + Jp * 16 + ((lane >> 4) << 3);
                uint32_t t[4];
                ldsm4t(t, cBh + off);
                bh[2*Jp][0] = t[0]; bh[2*Jp][1] = t[1];
                bh[2*Jp+1][0] = t[2]; bh[2*Jp+1][1] = t[3];
                ldsm4t(t, cBl + off);
                bl[2*Jp][0] = t[0]; bl[2*Jp][1] = t[1];
                bl[2*Jp+1][0] = t[2]; bl[2*Jp+1][1] = t[3];
            }
            #pragma unroll
            for (int mi = 0; mi < 4; ++mi)
                #pragma unroll
                for (int nj = 0; nj < 4; ++nj) {
                    mma_bf16(acc[mi][nj], ah[mi][0], ah[mi][1], ah[mi][2], ah[mi][3],
                             bh[nj][0], bh[nj][1]);
                    mma_bf16(acc[mi][nj], ah[mi][0], ah[mi][1], ah[mi][2], ah[mi][3],
                             bl[nj][0], bl[nj][1]);
                    mma_bf16(acc[mi][nj], al[mi][0], al[mi][1], al[mi][2], al[mi][3],
                             bh[nj][0], bh[nj][1]);
                }
        }

        // --- store converted B(k+1) ---
        if (more) {
            #pragma unroll
            for (int i = 0; i < 4; ++i)
                split_store4(nBh, nBl, (brow + i * 8) * 136 + bcol, vb[i]);
        }
        __syncthreads();
    }

    const int g  = lane >> 2;
    const int t2 = (lane & 3) * 2;
    #pragma unroll
    for (int mi = 0; mi < 4; ++mi)
        #pragma unroll
        for (int nj = 0; nj < 4; ++nj) {
            const int r = rB + m0 + mi * 16 + g;
            const int c = cB + n0 + nj * 8 + t2;
            const float b0 = bias[c], b1 = bias[c + 1];
            const float v00 = acc[mi][nj][0] + b0;
            const float v01 = acc[mi][nj][1] + b1;
            const float v10 = acc[mi][nj][2] + b0;
            const float v11 = acc[mi][nj][3] + b1;
            if (mode == 1) {
                Cout[(size_t)r * Ncols + c]           = v00;
                Cout[(size_t)r * Ncols + c + 1]       = v01;
                Cout[(size_t)(r + 8) * Ncols + c]     = v10;
                Cout[(size_t)(r + 8) * Ncols + c + 1] = v11;
            } else {
                const int which = c >> 10, rem = c & 1023;
                const int h = rem >> 6, d = rem & 63;
                __nv_bfloat16* dh = (which == 0) ? g_qh : (which == 1) ? g_kh : g_vh;
                __nv_bfloat16* dl = (which == 0) ? g_ql : (which == 1) ? g_kl : g_vl;
                const int b_  = r >> 11, n = r & 2047;
                const size_t ad0 = (((size_t)(b_ * HV + h)) * NV + n) * HDV + d;
                const size_t ad1 = ad0 + (size_t)8 * HDV;
                uint32_t hp, lp;
                packsplit(v00, v01, hp, lp);
                *reinterpret_cast<uint32_t*>(dh + ad0) = hp;
                *reinterpret_cast<uint32_t*>(dl + ad0) = lp;
                packsplit(v10, v11, hp, lp);
                *reinterpret_cast<uint32_t*>(dh + ad1) = hp;
                *reinterpret_cast<uint32_t*>(dl + ad1) = lp;
            }
        }
}

// ---------------------------------------------------------------------------
// Flash attention (R14, unchanged): 32-key tiles, cp.async 2-stage pipeline,
// 36 KB static smem, __launch_bounds__(256, 2) -> 128 regs, 2 CTAs/SM.
// ---------------------------------------------------------------------------
__global__ __launch_bounds__(256, 2) void flash_mma_kernel()
{
    __shared__ __nv_bfloat16 sm[18432];   // 36864 B = 2 stages

    const int tid  = threadIdx.x;
    const int lane = tid & 31;
    const int w    = tid >> 5;
    const int bh   = blockIdx.y;
    const int b    = bh >> 4, h = bh & 15;
    const int q0   = blockIdx.x * 128;
    const size_t base = (size_t)bh * NV * 64;
    const uint32_t smbase = (uint32_t)__cvta_generic_to_shared(sm);

    {
        const uint4* gh = reinterpret_cast<const uint4*>(g_qh + base + (size_t)q0 * 64);
        const uint4* gl = reinterpret_cast<const uint4*>(g_ql + base + (size_t)q0 * 64);
        #pragma unroll
        for (int i = 0; i < 4; ++i) {
            const int idx = tid + i * 256;
            const int row = idx >> 3, col8 = (idx & 7) * 8;
            *reinterpret_cast<uint4*>(&sm[row * 72 + col8])        = gh[idx];
            *reinterpret_cast<uint4*>(&sm[9216 + row * 72 + col8]) = gl[idx];
        }
    }
    __syncthreads();

    uint32_t qh[4][4], ql[4][4];
    #pragma unroll
    for (int kk = 0; kk < 4; ++kk) {
        const int off = (w * 16 + (lane & 15)) * 72 + kk * 16 + ((lane >> 4) << 3);
        ldsm4(qh[kk], sm + off);
        ldsm4(ql[kk], sm + 9216 + off);
    }
    __syncthreads();

    const __nv_bfloat16* gkh = g_kh + base;
    const __nv_bfloat16* gkl = g_kl + base;
    const __nv_bfloat16* gvh = g_vh + base;
    const __nv_bfloat16* gvl = g_vl + base;

    const int crow = tid >> 3, cseg = tid & 7;
    auto issue = [&](int kt) {
        const uint32_t sb = smbase + (kt & 1) * 18432u;
        const size_t src = (size_t)kt * 2048 + crow * 64 + cseg * 8;
        const uint32_t d = sb + (crow * 72 + cseg * 8) * 2;
        cpa16(d,          gkh + src);
        cpa16(d + 4608,   gkl + src);
        cpa16(d + 9216,   gvh + src);
        cpa16(d + 13824,  gvl + src);
        asm volatile("cp.async.commit_group;");
    };

    float m0 = -1e30f, m1 = -1e30f, l0 = 0.f, l1 = 0.f;
    float acc[8][4];
    #pragma unroll
    for (int j = 0; j < 8; ++j)
        #pragma unroll
        for (int r = 0; r < 4; ++r) acc[j][r] = 0.f;

    issue(0);
    for (int kt = 0; kt < NV / 32; ++kt) {
        if (kt + 1 < NV / 32) issue(kt + 1);
        else asm volatile("cp.async.commit_group;");
        asm volatile("cp.async.wait_group 1;");
        __syncthreads();

        const __nv_bfloat16* Kh = sm + (kt & 1) * 9216;
        const __nv_bfloat16* Kl = Kh + 2304;
        const __nv_bfloat16* Vh = Kh + 4608;
        const __nv_bfloat16* Vl = Kh + 6912;

        float s[4][4];
        #pragma unroll
        for (int j = 0; j < 4; ++j)
            #pragma unroll
            for (int r = 0; r < 4; ++r) s[j][r] = 0.f;

        #pragma unroll
        for (int kk = 0; kk < 4; ++kk) {
            #pragma unroll
            for (int J = 0; J < 2; ++J) {
                const int keyrow = J * 16 + (lane & 7) + ((lane >> 4) << 3);
                const int dim    = kk * 16 + (((lane >> 3) & 1) << 3);
                const int off    = keyrow * 72 + dim;
                uint32_t kbh[4], kbl[4];
                ldsm4(kbh, Kh + off);
                ldsm4(kbl, Kl + off);
                mma_bf16(s[2*J],   qh[kk][0], qh[kk][1], qh[kk][2], qh[kk][3], kbh[0], kbh[1]);
                mma_bf16(s[2*J],   qh[kk][0], qh[kk][1], qh[kk][2], qh[kk][3], kbl[0], kbl[1]);
                mma_bf16(s[2*J],   ql[kk][0], ql[kk][1], ql[kk][2], ql[kk][3], kbh[0], kbh[1]);
                mma_bf16(s[2*J+1], qh[kk][0], qh[kk][1], qh[kk][2], qh[kk][3], kbh[2], kbh[3]);
                mma_bf16(s[2*J+1], qh[kk][0], qh[kk][1], qh[kk][2], qh[kk][3], kbl[2], kbl[3]);
                mma_bf16(s[2*J+1], ql[kk][0], ql[kk][1], ql[kk][2], ql[kk][3], kbh[2], kbh[3]);
            }
        }

        float mx0 = -1e30f, mx1 = -1e30f;
        #pragma unroll
        for (int j = 0; j < 4; ++j) {
            #pragma unroll
            for (int r = 0; r < 4; ++r) s[j][r] *= SM_SCALE;
            mx0 = fmaxf(mx0, fmaxf(s[j][0], s[j][1]));
            mx1 = fmaxf(mx1, fmaxf(s[j][2], s[j][3]));
        }
        mx0 = fmaxf(mx0, __shfl_xor_sync(0xffffffffu, mx0, 1));
        mx0 = fmaxf(mx0, __shfl_xor_sync(0xffffffffu, mx0, 2));
        mx1 = fmaxf(mx1, __shfl_xor_sync(0xffffffffu, mx1, 1));
        mx1 = fmaxf(mx1, __shfl_xor_sync(0xffffffffu, mx1, 2));
        const float mn0 = fmaxf(m0, mx0), mn1 = fmaxf(m1, mx1);
        const float al0 = ex2f(m0 - mn0), al1 = ex2f(m1 - mn1);
        l0 *= al0; l1 *= al1;
        #pragma unroll
        for (int j = 0; j < 8; ++j) {
            acc[j][0] *= al0; acc[j][1] *= al0;
            acc[j][2] *= al1; acc[j][3] *= al1;
        }
        #pragma unroll
        for (int j = 0; j < 4; ++j) {
            s[j][0] = ex2f(s[j][0] - mn0);
            s[j][1] = ex2f(s[j][1] - mn0);
            s[j][2] = ex2f(s[j][2] - mn1);
            s[j][3] = ex2f(s[j][3] - mn1);
            l0 += s[j][0] + s[j][1];
            l1 += s[j][2] + s[j][3];
        }
        m0 = mn0; m1 = mn1;

        #pragma unroll
        for (int kk = 0; kk < 2; ++kk) {
            uint32_t pah[4], pal[4];
            packsplit(s[2*kk][0],   s[2*kk][1],   pah[0], pal[0]);
            packsplit(s[2*kk][2],   s[2*kk][3],   pah[1], pal[1]);
            packsplit(s[2*kk+1][0], s[2*kk+1][1], pah[2], pal[2]);
            packsplit(s[2*kk+1][2], s[2*kk+1][3], pah[3], pal[3]);
            #pragma unroll
            for (int J = 0; J < 4; ++J) {
                const int key = kk * 16 + (lane & 15);
                const int dim = J * 16 + ((lane >> 4) << 3);
                const int off = key * 72 + dim;
                uint32_t vbh[4], vbl[4];
                ldsm4t(vbh, Vh + off);
                ldsm4t(vbl, Vl + off);
                mma_bf16(acc[2*J],   pah[0], pah[1], pah[2], pah[3], vbh[0], vbh[1]);
                mma_bf16(acc[2*J],   pah[0], pah[1], pah[2], pah[3], vbl[0], vbl[1]);
                mma_bf16(acc[2*J],   pal[0], pal[1], pal[2], pal[3], vbh[0], vbh[1]);
                mma_bf16(acc[2*J+1], pah[0], pah[1], pah[2], pah[3], vbh[2], vbh[3]);
                mma_bf16(acc[2*J+1], pah[0], pah[1], pah[2], pah[3], vbl[2], vbl[3]);
                mma_bf16(acc[2*J+1], pal[0], pal[1], pal[2], pal[3], vbh[2], vbh[3]);
            }
        }
        __syncthreads();
    }

    l0 += __shfl_xor_sync(0xffffffffu, l0, 1);
    l0 += __shfl_xor_sync(0xffffffffu, l0, 2);
    l1 += __shfl_xor_sync(0xffffffffu, l1, 1);
    l1 += __shfl_xor_sync(0xffffffffu, l1, 2);
    const float inv0 = 1.f / l0, inv1 = 1.f / l1;

    const int g  = lane >> 2;
    const int t2 = (lane & 3) * 2;
    const int row0 = q0 + w * 16 + g;
    const size_t ob = ((size_t)b * NV + row0) * CV + h * 64;
    #pragma unroll
    for (int j = 0; j < 8; ++j) {
        const int c = j * 8 + t2;
        *reinterpret_cast<float2*>(&g_o[ob + c]) =
            make_float2(acc[j][0] * inv0, acc[j][1] * inv0);
        *reinterpret_cast<float2*>(&g_o[ob + (size_t)8 * CV + c]) =
            make_float2(acc[j][2] * inv1, acc[j][3] * inv1);
    }
}

// ---------------------------------------------------------------------------
extern "C" void kernel_launch(void* const* d_in, const int* in_sizes, int n_in,
                              void* d_out, int out_size)
{
    const float* x      = (const float*)d_in[0];
    const float* w_qkv  = (const float*)d_in[1];
    const float* b_qkv  = (const float*)d_in[2];
    const float* a_q    = (const float*)d_in[3];
    const float* b_q    = (const float*)d_in[4];
    const float* a_v    = (const float*)d_in[5];
    const float* b_v    = (const float*)d_in[6];
    const float* w_proj = (const float*)d_in[7];
    const float* b_proj = (const float*)d_in[8];
    float* out = (float*)d_out;

    (void)in_sizes; (void)n_in; (void)out_size;

    cudaFuncSetAttribute(gemm3_kernel,
        cudaFuncAttributeMaxDynamicSharedMemorySize, GSMEM);

    // 0) fold LoRA into QKV weights/bias
    prep_w_kernel<<<dim3(48, 16), 256>>>(w_qkv, a_q, b_q, a_v, b_v);
    prep_b_kernel<<<48, 64>>>(b_qkv, a_q, b_q, a_v, b_v);

    // 1) QKV GEMM (double-buffered split-bf16 TC) -> split q/k/v
    gemm3_kernel<<<dim3(3 * CV / 128, MROWS / 128), 256, GSMEM>>>(
        x, nullptr, nullptr, out, 3 * CV, 0);

    // 2) attention (TC, 32-key cp.async pipeline, 2 CTAs/SM) -> g_o
    flash_mma_kernel<<<dim3(NV / 128, BV * HV), 256>>>();

    // 3) projection (double-buffered split-bf16 TC) -> out
    gemm3_kernel<<<dim3(CV / 128, MROWS / 128), 256, GSMEM>>>(
        nullptr, w_proj, b_proj, out, CV, 1);
}

// round 17
// speedup vs baseline: 1.0663x; 1.0663x over previous
#include <cuda_runtime.h>
#include <cuda_bf16.h>
#include <math.h>
#include <stdint.h>

// Problem constants
#define BV   2
#define NV   2048
#define CV   1024
#define HV   16
#define HDV  64
#define MROWS (BV*NV)            // 4096
#define SM_SCALE 0.1803368801f   // 64^-0.5 * log2(e)
#define BHND ((size_t)BV*HV*NV*HDV)

// scratch
__device__ float g_o[(size_t)MROWS*CV];           // attention output fp32
__device__ float g_w2[(size_t)CV*3*CV];           // LoRA-folded QKV weight
__device__ float g_b2[3*CV];                      // LoRA-folded QKV bias
// split-bf16 q/k/v (hi + lo residual), layout [B,H,N,HD]
__device__ __nv_bfloat16 g_qh[BHND], g_ql[BHND];
__device__ __nv_bfloat16 g_kh[BHND], g_kl[BHND];
__device__ __nv_bfloat16 g_vh[BHND], g_vl[BHND];

// ---------------------------------------------------------------------------
// helpers
// ---------------------------------------------------------------------------
__device__ __forceinline__ void ldsm4(uint32_t r[4], const void* p) {
    uint32_t a = (uint32_t)__cvta_generic_to_shared(p);
    asm volatile("ldmatrix.sync.aligned.m8n8.x4.shared.b16 {%0,%1,%2,%3},[%4];"
        : "=r"(r[0]), "=r"(r[1]), "=r"(r[2]), "=r"(r[3]) : "r"(a));
}
__device__ __forceinline__ void ldsm4t(uint32_t r[4], const void* p) {
    uint32_t a = (uint32_t)__cvta_generic_to_shared(p);
    asm volatile("ldmatrix.sync.aligned.m8n8.x4.trans.shared.b16 {%0,%1,%2,%3},[%4];"
        : "=r"(r[0]), "=r"(r[1]), "=r"(r[2]), "=r"(r[3]) : "r"(a));
}
__device__ __forceinline__ void mma_bf16(float d[4],
    uint32_t a0, uint32_t a1, uint32_t a2, uint32_t a3, uint32_t b0, uint32_t b1)
{
    asm volatile(
        "mma.sync.aligned.m16n8k16.row.col.f32.bf16.bf16.f32 "
        "{%0,%1,%2,%3},{%4,%5,%6,%7},{%8,%9},{%0,%1,%2,%3};"
        : "+f"(d[0]), "+f"(d[1]), "+f"(d[2]), "+f"(d[3])
        : "r"(a0), "r"(a1), "r"(a2), "r"(a3), "r"(b0), "r"(b1));
}
__device__ __forceinline__ float ex2f(float x) {
    float r; asm("ex2.approx.ftz.f32 %0,%1;" : "=f"(r) : "f"(x)); return r;
}
__device__ __forceinline__ void packsplit(float x, float y, uint32_t& hp, uint32_t& lp)
{
    __nv_bfloat162 h = __floats2bfloat162_rn(x, y);
    __nv_bfloat162 l = __floats2bfloat162_rn(x - __bfloat162float(h.x),
                                             y - __bfloat162float(h.y));
    hp = *reinterpret_cast<uint32_t*>(&h);
    lp = *reinterpret_cast<uint32_t*>(&l);
}
__device__ __forceinline__ void split_store4(__nv_bfloat16* H, __nv_bfloat16* L,
                                             int off, float4 v)
{
    __nv_bfloat162 h0 = __floats2bfloat162_rn(v.x, v.y);
    __nv_bfloat162 h1 = __floats2bfloat162_rn(v.z, v.w);
    __nv_bfloat162 l0 = __floats2bfloat162_rn(v.x - __bfloat162float(h0.x),
                                              v.y - __bfloat162float(h0.y));
    __nv_bfloat162 l1 = __floats2bfloat162_rn(v.z - __bfloat162float(h1.x),
                                              v.w - __bfloat162float(h1.y));
    *reinterpret_cast<__nv_bfloat162*>(H + off)     = h0;
    *reinterpret_cast<__nv_bfloat162*>(H + off + 2) = h1;
    *reinterpret_cast<__nv_bfloat162*>(L + off)     = l0;
    *reinterpret_cast<__nv_bfloat162*>(L + off + 2) = l1;
}
__device__ __forceinline__ void cpa16(uint32_t dsh, const void* src) {
    asm volatile("cp.async.cg.shared.global [%0], [%1], 16;" :: "r"(dsh), "l"(src));
}

// ---------------------------------------------------------------------------
// prep: fold LoRA into QKV weights AND bias.  W'[:, blk] = W[:, blk] @ M,
// b'[blk] = b[blk] @ M, with M = I + 2*A@B (in shared Ms).  K cols copied.
// grid (48, 16), 256 threads.  Bias handled by r0==0 blocks.
// ---------------------------------------------------------------------------
__global__ __launch_bounds__(256) void prep_w_kernel(
    const float* __restrict__ W, const float* __restrict__ bqkv,
    const float* __restrict__ aq, const float* __restrict__ bq,
    const float* __restrict__ av, const float* __restrict__ bv)
{
    __shared__ float Ws[64][65];
    __shared__ float Ms[64][65];

    const int tid = threadIdx.x;
    const int c0  = blockIdx.x * 64;
    const int r0  = blockIdx.y * 64;
    const int which = c0 >> 10;          // 0=q,1=k,2=v

    if (which == 1) {
        if (r0 == 0 && tid < 64) g_b2[c0 + tid] = bqkv[c0 + tid];
        for (int ii = 0; ii < 4; ++ii) {
            const int idx = tid + ii * 256;
            const int i = idx >> 4, e4 = (idx & 15) * 4;
            float4 v = *reinterpret_cast<const float4*>(
                W + (size_t)(r0 + i) * 3072 + c0 + e4);
            *reinterpret_cast<float4*>(
                g_w2 + (size_t)(r0 + i) * 3072 + c0 + e4) = v;
        }
        return;
    }
    const float* A  = (which == 0) ? aq : av;
    const float* Bm = (which == 0) ? bq : bv;

    for (int ii = 0; ii < 4; ++ii) {
        const int idx = tid + ii * 256;
        const int i = idx >> 4, e4 = (idx & 15) * 4;
        float4 v = *reinterpret_cast<const float4*>(
            W + (size_t)(r0 + i) * 3072 + c0 + e4);
        Ws[i][e4+0]=v.x; Ws[i][e4+1]=v.y; Ws[i][e4+2]=v.z; Ws[i][e4+3]=v.w;
    }
    for (int ii = 0; ii < 16; ++ii) {
        const int idx = tid + ii * 256;
        const int e = idx >> 6, d = idx & 63;
        float s = 0.f;
        for (int r = 0; r < 16; ++r) s += A[e * 16 + r] * Bm[r * 64 + d];
        Ms[e][d] = (e == d ? 1.f : 0.f) + 2.f * s;
    }
    __syncthreads();

    const int i  = tid & 63;
    const int dg = tid >> 6;
    for (int jj = 0; jj < 16; ++jj) {
        const int col = dg * 16 + jj;
        float acc = 0.f;
        for (int e = 0; e < 64; ++e) acc += Ws[i][e] * Ms[e][col];
        g_w2[(size_t)(r0 + i) * 3072 + c0 + col] = acc;
    }
    // bias fold: b'[c0+d] = sum_e b[c0+e] * M[e][d]   (M already in Ms)
    if (r0 == 0 && tid < 64) {
        float acc = 0.f;
        for (int e = 0; e < 64; ++e) acc += bqkv[c0 + e] * Ms[e][tid];
        g_b2[c0 + tid] = acc;
    }
}

// ---------------------------------------------------------------------------
// split-bf16 GEMM, K-step 64 (R15 structure, half the sync walls).
// Block 128x128, 8 warps, dynamic smem 71680 B, 2 CTAs/SM.
// Bin == nullptr -> B = g_w2, bias = g_b2.  Ain == nullptr -> A = g_o.
// mode 0: split-convert + store bf16 hi/lo into g_{q,k,v}{h,l}.
// mode 1: fp32 store to Cout.
// smem (halves): sAh 0..9216 (128x72), sAl ..18432,
//                sBh ..27136 (64x136), sBl ..35840
// ---------------------------------------------------------------------------
#define GSMEM (35840 * 2)   // 71680 bytes

__global__ __launch_bounds__(256, 2) void gemm3_kernel(
    const float* __restrict__ Ain, const float* __restrict__ Bin,
    const float* __restrict__ biasin, float* __restrict__ Cout,
    int Ncols, int mode)
{
    extern __shared__ __nv_bfloat16 sm[];
    __nv_bfloat16* sAh = sm;
    __nv_bfloat16* sAl = sm + 9216;
    __nv_bfloat16* sBh = sm + 18432;
    __nv_bfloat16* sBl = sm + 27136;

    const float* A    = Ain ? Ain : g_o;
    const float* B    = Bin ? Bin : g_w2;
    const float* bias = Bin ? biasin : g_b2;

    const int tid  = threadIdx.x;
    const int lane = tid & 31;
    const int warp = tid >> 5;
    const int m0   = (warp >> 2) * 64;
    const int n0   = (warp & 3) * 32;
    const int rB   = blockIdx.y * 128;
    const int cB   = blockIdx.x * 128;

    float acc[4][4][4];
    #pragma unroll
    for (int i = 0; i < 4; ++i)
        #pragma unroll
        for (int j = 0; j < 4; ++j)
            #pragma unroll
            for (int r = 0; r < 4; ++r) acc[i][j][r] = 0.f;

    for (int k0 = 0; k0 < 1024; k0 += 64) {
        __syncthreads();
        // A tile: 128 x 64 fp32 = 2048 float4
        #pragma unroll
        for (int i = 0; i < 8; ++i) {
            const int idx = tid + i * 256;
            const int r = idx >> 4, f4 = (idx & 15) * 4;
            float4 v = *reinterpret_cast<const float4*>(
                A + (size_t)(rB + r) * 1024 + k0 + f4);
            split_store4(sAh, sAl, r * 72 + f4, v);
        }
        // B tile: 64 x 128 fp32 = 2048 float4
        #pragma unroll
        for (int i = 0; i < 8; ++i) {
            const int idx = tid + i * 256;
            const int r = idx >> 5, f4 = (idx & 31) * 4;
            float4 v = *reinterpret_cast<const float4*>(
                B + (size_t)(k0 + r) * Ncols + cB + f4);
            split_store4(sBh, sBl, r * 136 + f4, v);
        }
        __syncthreads();

        #pragma unroll
        for (int ks = 0; ks < 4; ++ks) {
            uint32_t ah[4][4], al[4][4];
            #pragma unroll
            for (int mi = 0; mi < 4; ++mi) {
                const int off = (m0 + mi * 16 + (lane & 15)) * 72
                              + ks * 16 + ((lane >> 4) << 3);
                ldsm4(ah[mi], sAh + off);
                ldsm4(al[mi], sAl + off);
            }
            uint32_t bh[4][2], bl[4][2];
            #pragma unroll
            for (int Jp = 0; Jp < 2; ++Jp) {
                const int off = (ks * 16 + (lane & 15)) * 136
                              + n0 + Jp * 16 + ((lane >> 4) << 3);
                uint32_t t[4];
                ldsm4t(t, sBh + off);
                bh[2*Jp][0] = t[0]; bh[2*Jp][1] = t[1];
                bh[2*Jp+1][0] = t[2]; bh[2*Jp+1][1] = t[3];
                ldsm4t(t, sBl + off);
                bl[2*Jp][0] = t[0]; bl[2*Jp][1] = t[1];
                bl[2*Jp+1][0] = t[2]; bl[2*Jp+1][1] = t[3];
            }
            #pragma unroll
            for (int mi = 0; mi < 4; ++mi)
                #pragma unroll
                for (int nj = 0; nj < 4; ++nj) {
                    mma_bf16(acc[mi][nj], ah[mi][0], ah[mi][1], ah[mi][2], ah[mi][3],
                             bh[nj][0], bh[nj][1]);
                    mma_bf16(acc[mi][nj], ah[mi][0], ah[mi][1], ah[mi][2], ah[mi][3],
                             bl[nj][0], bl[nj][1]);
                    mma_bf16(acc[mi][nj], al[mi][0], al[mi][1], al[mi][2], al[mi][3],
                             bh[nj][0], bh[nj][1]);
                }
        }
    }

    const int g  = lane >> 2;
    const int t2 = (lane & 3) * 2;
    #pragma unroll
    for (int mi = 0; mi < 4; ++mi)
        #pragma unroll
        for (int nj = 0; nj < 4; ++nj) {
            const int r = rB + m0 + mi * 16 + g;
            const int c = cB + n0 + nj * 8 + t2;
            const float b0 = bias[c], b1 = bias[c + 1];
            const float v00 = acc[mi][nj][0] + b0;
            const float v01 = acc[mi][nj][1] + b1;
            const float v10 = acc[mi][nj][2] + b0;
            const float v11 = acc[mi][nj][3] + b1;
            if (mode == 1) {
                Cout[(size_t)r * Ncols + c]           = v00;
                Cout[(size_t)r * Ncols + c + 1]       = v01;
                Cout[(size_t)(r + 8) * Ncols + c]     = v10;
                Cout[(size_t)(r + 8) * Ncols + c + 1] = v11;
            } else {
                const int which = c >> 10, rem = c & 1023;
                const int h = rem >> 6, d = rem & 63;
                __nv_bfloat16* dh = (which == 0) ? g_qh : (which == 1) ? g_kh : g_vh;
                __nv_bfloat16* dl = (which == 0) ? g_ql : (which == 1) ? g_kl : g_vl;
                const int b_  = r >> 11, n = r & 2047;
                const size_t ad0 = (((size_t)(b_ * HV + h)) * NV + n) * HDV + d;
                const size_t ad1 = ad0 + (size_t)8 * HDV;
                uint32_t hp, lp;
                packsplit(v00, v01, hp, lp);
                *reinterpret_cast<uint32_t*>(dh + ad0) = hp;
                *reinterpret_cast<uint32_t*>(dl + ad0) = lp;
                packsplit(v10, v11, hp, lp);
                *reinterpret_cast<uint32_t*>(dh + ad1) = hp;
                *reinterpret_cast<uint32_t*>(dl + ad1) = lp;
            }
        }
}

// ---------------------------------------------------------------------------
// Flash attention (R14, unchanged): 32-key tiles, cp.async 2-stage pipeline,
// 36 KB static smem, __launch_bounds__(256, 2) -> 128 regs, 2 CTAs/SM.
// ---------------------------------------------------------------------------
__global__ __launch_bounds__(256, 2) void flash_mma_kernel()
{
    __shared__ __nv_bfloat16 sm[18432];   // 36864 B = 2 stages

    const int tid  = threadIdx.x;
    const int lane = tid & 31;
    const int w    = tid >> 5;
    const int bh   = blockIdx.y;
    const int b    = bh >> 4, h = bh & 15;
    const int q0   = blockIdx.x * 128;
    const size_t base = (size_t)bh * NV * 64;
    const uint32_t smbase = (uint32_t)__cvta_generic_to_shared(sm);

    {
        const uint4* gh = reinterpret_cast<const uint4*>(g_qh + base + (size_t)q0 * 64);
        const uint4* gl = reinterpret_cast<const uint4*>(g_ql + base + (size_t)q0 * 64);
        #pragma unroll
        for (int i = 0; i < 4; ++i) {
            const int idx = tid + i * 256;
            const int row = idx >> 3, col8 = (idx & 7) * 8;
            *reinterpret_cast<uint4*>(&sm[row * 72 + col8])        = gh[idx];
            *reinterpret_cast<uint4*>(&sm[9216 + row * 72 + col8]) = gl[idx];
        }
    }
    __syncthreads();

    uint32_t qh[4][4], ql[4][4];
    #pragma unroll
    for (int kk = 0; kk < 4; ++kk) {
        const int off = (w * 16 + (lane & 15)) * 72 + kk * 16 + ((lane >> 4) << 3);
        ldsm4(qh[kk], sm + off);
        ldsm4(ql[kk], sm + 9216 + off);
    }
    __syncthreads();

    const __nv_bfloat16* gkh = g_kh + base;
    const __nv_bfloat16* gkl = g_kl + base;
    const __nv_bfloat16* gvh = g_vh + base;
    const __nv_bfloat16* gvl = g_vl + base;

    const int crow = tid >> 3, cseg = tid & 7;
    auto issue = [&](int kt) {
        const uint32_t sb = smbase + (kt & 1) * 18432u;
        const size_t src = (size_t)kt * 2048 + crow * 64 + cseg * 8;
        const uint32_t d = sb + (crow * 72 + cseg * 8) * 2;
        cpa16(d,          gkh + src);
        cpa16(d + 4608,   gkl + src);
        cpa16(d + 9216,   gvh + src);
        cpa16(d + 13824,  gvl + src);
        asm volatile("cp.async.commit_group;");
    };

    float m0 = -1e30f, m1 = -1e30f, l0 = 0.f, l1 = 0.f;
    float acc[8][4];
    #pragma unroll
    for (int j = 0; j < 8; ++j)
        #pragma unroll
        for (int r = 0; r < 4; ++r) acc[j][r] = 0.f;

    issue(0);
    for (int kt = 0; kt < NV / 32; ++kt) {
        if (kt + 1 < NV / 32) issue(kt + 1);
        else asm volatile("cp.async.commit_group;");
        asm volatile("cp.async.wait_group 1;");
        __syncthreads();

        const __nv_bfloat16* Kh = sm + (kt & 1) * 9216;
        const __nv_bfloat16* Kl = Kh + 2304;
        const __nv_bfloat16* Vh = Kh + 4608;
        const __nv_bfloat16* Vl = Kh + 6912;

        float s[4][4];
        #pragma unroll
        for (int j = 0; j < 4; ++j)
            #pragma unroll
            for (int r = 0; r < 4; ++r) s[j][r] = 0.f;

        #pragma unroll
        for (int kk = 0; kk < 4; ++kk) {
            #pragma unroll
            for (int J = 0; J < 2; ++J) {
                const int keyrow = J * 16 + (lane & 7) + ((lane >> 4) << 3);
                const int dim    = kk * 16 + (((lane >> 3) & 1) << 3);
                const int off    = keyrow * 72 + dim;
                uint32_t kbh[4], kbl[4];
                ldsm4(kbh, Kh + off);
                ldsm4(kbl, Kl + off);
                mma_bf16(s[2*J],   qh[kk][0], qh[kk][1], qh[kk][2], qh[kk][3], kbh[0], kbh[1]);
                mma_bf16(s[2*J],   qh[kk][0], qh[kk][1], qh[kk][2], qh[kk][3], kbl[0], kbl[1]);
                mma_bf16(s[2*J],   ql[kk][0], ql[kk][1], ql[kk][2], ql[kk][3], kbh[0], kbh[1]);
                mma_bf16(s[2*J+1], qh[kk][0], qh[kk][1], qh[kk][2], qh[kk][3], kbh[2], kbh[3]);
                mma_bf16(s[2*J+1], qh[kk][0], qh[kk][1], qh[kk][2], qh[kk][3], kbl[2], kbl[3]);
                mma_bf16(s[2*J+1], ql[kk][0], ql[kk][1], ql[kk][2], ql[kk][3], kbh[2], kbh[3]);
            }
        }

        float mx0 = -1e30f, mx1 = -1e30f;
        #pragma unroll
        for (int j = 0; j < 4; ++j) {
            #pragma unroll
            for (int r = 0; r < 4; ++r) s[j][r] *= SM_SCALE;
            mx0 = fmaxf(mx0, fmaxf(s[j][0], s[j][1]));
            mx1 = fmaxf(mx1, fmaxf(s[j][2], s[j][3]));
        }
        mx0 = fmaxf(mx0, __shfl_xor_sync(0xffffffffu, mx0, 1));
        mx0 = fmaxf(mx0, __shfl_xor_sync(0xffffffffu, mx0, 2));
        mx1 = fmaxf(mx1, __shfl_xor_sync(0xffffffffu, mx1, 1));
        mx1 = fmaxf(mx1, __shfl_xor_sync(0xffffffffu, mx1, 2));
        const float mn0 = fmaxf(m0, mx0), mn1 = fmaxf(m1, mx1);
        const float al0 = ex2f(m0 - mn0), al1 = ex2f(m1 - mn1);
        l0 *= al0; l1 *= al1;
        #pragma unroll
        for (int j = 0; j < 8; ++j) {
            acc[j][0] *= al0; acc[j][1] *= al0;
            acc[j][2] *= al1; acc[j][3] *= al1;
        }
        #pragma unroll
        for (int j = 0; j < 4; ++j) {
            s[j][0] = ex2f(s[j][0] - mn0);
            s[j][1] = ex2f(s[j][1] - mn0);
            s[j][2] = ex2f(s[j][2] - mn1);
            s[j][3] = ex2f(s[j][3] - mn1);
            l0 += s[j][0] + s[j][1];
            l1 += s[j][2] + s[j][3];
        }
        m0 = mn0; m1 = mn1;

        #pragma unroll
        for (int kk = 0; kk < 2; ++kk) {
            uint32_t pah[4], pal[4];
            packsplit(s[2*kk][0],   s[2*kk][1],   pah[0], pal[0]);
            packsplit(s[2*kk][2],   s[2*kk][3],   pah[1], pal[1]);
            packsplit(s[2*kk+1][0], s[2*kk+1][1], pah[2], pal[2]);
            packsplit(s[2*kk+1][2], s[2*kk+1][3], pah[3], pal[3]);
            #pragma unroll
            for (int J = 0; J < 4; ++J) {
                const int key = kk * 16 + (lane & 15);
                const int dim = J * 16 + ((lane >> 4) << 3);
                const int off = key * 72 + dim;
                uint32_t vbh[4], vbl[4];
                ldsm4t(vbh, Vh + off);
                ldsm4t(vbl, Vl + off);
                mma_bf16(acc[2*J],   pah[0], pah[1], pah[2], pah[3], vbh[0], vbh[1]);
                mma_bf16(acc[2*J],   pah[0], pah[1], pah[2], pah[3], vbl[0], vbl[1]);
                mma_bf16(acc[2*J],   pal[0], pal[1], pal[2], pal[3], vbh[0], vbh[1]);
                mma_bf16(acc[2*J+1], pah[0], pah[1], pah[2], pah[3], vbh[2], vbh[3]);
                mma_bf16(acc[2*J+1], pah[0], pah[1], pah[2], pah[3], vbl[2], vbl[3]);
                mma_bf16(acc[2*J+1], pal[0], pal[1], pal[2], pal[3], vbh[2], vbh[3]);
            }
        }
        __syncthreads();
    }

    l0 += __shfl_xor_sync(0xffffffffu, l0, 1);
    l0 += __shfl_xor_sync(0xffffffffu, l0, 2);
    l1 += __shfl_xor_sync(0xffffffffu, l1, 1);
    l1 += __shfl_xor_sync(0xffffffffu, l1, 2);
    const float inv0 = 1.f / l0, inv1 = 1.f / l1;

    const int g  = lane >> 2;
    const int t2 = (lane & 3) * 2;
    const int row0 = q0 + w * 16 + g;
    const size_t ob = ((size_t)b * NV + row0) * CV + h * 64;
    #pragma unroll
    for (int j = 0; j < 8; ++j) {
        const int c = j * 8 + t2;
        *reinterpret_cast<float2*>(&g_o[ob + c]) =
            make_float2(acc[j][0] * inv0, acc[j][1] * inv0);
        *reinterpret_cast<float2*>(&g_o[ob + (size_t)8 * CV + c]) =
            make_float2(acc[j][2] * inv1, acc[j][3] * inv1);
    }
}

// ---------------------------------------------------------------------------
extern "C" void kernel_launch(void* const* d_in, const int* in_sizes, int n_in,
                              void* d_out, int out_size)
{
    const float* x      = (const float*)d_in[0];
    const float* w_qkv  = (const float*)d_in[1];
    const float* b_qkv  = (const float*)d_in[2];
    const float* a_q    = (const float*)d_in[3];
    const float* b_q    = (const float*)d_in[4];
    const float* a_v    = (const float*)d_in[5];
    const float* b_v    = (const float*)d_in[6];
    const float* w_proj = (const float*)d_in[7];
    const float* b_proj = (const float*)d_in[8];
    float* out = (float*)d_out;

    (void)in_sizes; (void)n_in; (void)out_size;

    cudaFuncSetAttribute(gemm3_kernel,
        cudaFuncAttributeMaxDynamicSharedMemorySize, GSMEM);

    // 0) fold LoRA into QKV weights + bias (single kernel)
    prep_w_kernel<<<dim3(48, 16), 256>>>(w_qkv, b_qkv, a_q, b_q, a_v, b_v);

    // 1) QKV GEMM (split-bf16 TC, K-step 64, 2 CTAs/SM) -> split q/k/v
    gemm3_kernel<<<dim3(3 * CV / 128, MROWS / 128), 256, GSMEM>>>(
        x, nullptr, nullptr, out, 3 * CV, 0);

    // 2) attention (TC, 32-key cp.async pipeline, 2 CTAs/SM) -> g_o
    flash_mma_kernel<<<dim3(NV / 128, BV * HV), 256>>>();

    // 3) projection (split-bf16 TC, K-step 64, 2 CTAs/SM) -> out
    gemm3_kernel<<<dim3(CV / 128, MROWS / 128), 256, GSMEM>>>(
        nullptr, w_proj, b_proj, out, CV, 1);
}